// round 16
// baseline (speedup 1.0000x reference)
#include <cuda_runtime.h>
#include <math.h>
#include <stdint.h>

// ConvolutionalCapsule EM routing, R11: 768 threads/CTA (24 warps, 6/SMSP),
// register votes with 6-i x 2-row ownership (24 ull vote regs/thread).
// t = h*32 + om*2 + pd, h in 0..23, i = h*6 + j. Pre-transposed w (g_wT) for
// coalesced build loads; sqrt-free stats; paired-lane softmax.
// One CTA per output position (1152 CTAs).

#define EPS 1e-9f
#define LOG2E 1.4426950408889634f
#define NPOS 1152
#define ICAP 144

// smem float offsets
#define OFF_RR    0        // [144][16] rr (softmax output)
#define OFF_ACTS  2304     // [144] (+pad)
#define OFF_BASE  2464     // [16] int row-base table (9 used)
#define OFF_PC1   2480     // S1: [24][256]  (h, om*16+p)
#define OFF_PC2   8624     // S2: [24][256]
#define OFF_PC0   14768    // S0: [24][32]   (h, om*2+pd)
#define OFF_EP    15536    // [144][36] E-step cells (om*2+pd, padded)
#define OFF_A     20720    // [256] av  (o*16+p)
#define OFF_B     20976    // [256] bco
#define OFF_C     21232    // [16]
#define SMEM_FLOATS 21248
#define SMEM_BYTES (SMEM_FLOATS * 4)

typedef unsigned long long ull;

// transposed weights: wT[i][r][om] as float4 (ulonglong2) blocks
__device__ ulonglong2 g_wT[144 * 64];

__device__ __forceinline__ ull pk2(float lo, float hi) {
    ull d;
    asm("mov.b64 %0, {%1, %2};" : "=l"(d)
        : "r"(__float_as_uint(lo)), "r"(__float_as_uint(hi)));
    return d;
}
__device__ __forceinline__ void upk2(ull v, float& lo, float& hi) {
    unsigned a, b;
    asm("mov.b64 {%0, %1}, %2;" : "=r"(a), "=r"(b) : "l"(v));
    lo = __uint_as_float(a); hi = __uint_as_float(b);
}
__device__ __forceinline__ ull fma2(ull a, ull b, ull c) {
    ull d; asm("fma.rn.f32x2 %0, %1, %2, %3;" : "=l"(d) : "l"(a), "l"(b), "l"(c));
    return d;
}
__device__ __forceinline__ ull mul2(ull a, ull b) {
    ull d; asm("mul.rn.f32x2 %0, %1, %2;" : "=l"(d) : "l"(a), "l"(b));
    return d;
}
__device__ __forceinline__ ull add2(ull a, ull b) {
    ull d; asm("add.rn.f32x2 %0, %1, %2;" : "=l"(d) : "l"(a), "l"(b));
    return d;
}

__global__ void transpose_w_kernel(const float* __restrict__ w) {
    const int idx = blockIdx.x * 256 + threadIdx.x;   // 9216 float4s
    if (idx < 144 * 64) {
        const int i  = idx >> 6;
        const int rm = idx & 63;
        const int r  = rm >> 4;
        const int om = rm & 15;
        g_wT[idx] = ((const ulonglong2*)w)[i * 64 + om * 4 + r];
    }
}

__global__ __launch_bounds__(768, 1)
void caps_em_kernel(const float* __restrict__ pose_in,   // [8,14,14,256]
                    const float* __restrict__ act_in,    // [8,14,14,16]
                    const float* __restrict__ beta_v,    // [16]
                    const float* __restrict__ beta_a,    // [16]
                    float* __restrict__ out)             // pose[1152,256] ++ act[1152,16]
{
    extern __shared__ float sm[];
    float* rr    = sm + OFF_RR;
    float* acts  = sm + OFF_ACTS;
    int*   baseK = (int*)(sm + OFF_BASE);
    float* pc1   = sm + OFF_PC1;
    float* pc2   = sm + OFF_PC2;
    float* pc0   = sm + OFF_PC0;
    float* ep    = sm + OFF_EP;
    float* a_sm  = sm + OFF_A;
    float* b_sm  = sm + OFF_B;
    float* c_sm  = sm + OFF_C;

    const int n = blockIdx.x;
    const int x = n % 12;
    const int y = (n / 12) % 12;
    const int b = n / 144;
    const int t = threadIdx.x;

    const int h  = t >> 5;          // 0..23: i = h*6 + j
    const int om = (t >> 1) & 15;   // output capsule
    const int pd = t & 1;           // row pair: rows 2pd, 2pd+1
    const int i0 = h * 6;
    // stats mapping (t < 256)
    const int os = t >> 4;
    const int ps = t & 15;

    // ---- row-base table (9 kernel positions) ----
    if (t < 9)
        baseK[t] = (b * 14 + (y + t / 3)) * 14 + (x + t % 3);
    __syncthreads();

    // ---- stage acts ----
    if (t < ICAP)
        acts[t] = act_in[baseK[t >> 4] * 16 + (t & 15)];

    // ---- build votes into registers (rows 2pd, 2pd+1 of 6 capsules) ----
    ull vA0[6], vA1[6], vB0[6], vB1[6];
    #pragma unroll
    for (int j = 0; j < 6; ++j) {
        const int i = i0 + j;
        const float* pp = pose_in + (size_t)baseK[i >> 4] * 256 + (i & 15) * 16 + pd * 8;
        const float4 pr0 = *(const float4*)pp;
        const float4 pr1 = *(const float4*)(pp + 4);
        const ulonglong2* wt = g_wT + (size_t)i * 64 + om;
        const ulonglong2 w0 = wt[0], w1 = wt[16], w2 = wt[32], w3 = wt[48];
        {
            const ull a0 = pk2(pr0.x, pr0.x), a1 = pk2(pr0.y, pr0.y);
            const ull a2 = pk2(pr0.z, pr0.z), a3 = pk2(pr0.w, pr0.w);
            ull s01 = mul2(a0, w0.x), s23 = mul2(a0, w0.y);
            s01 = fma2(a1, w1.x, s01);  s23 = fma2(a1, w1.y, s23);
            s01 = fma2(a2, w2.x, s01);  s23 = fma2(a2, w2.y, s23);
            s01 = fma2(a3, w3.x, s01);  s23 = fma2(a3, w3.y, s23);
            vA0[j] = s01; vA1[j] = s23;
        }
        {
            const ull a0 = pk2(pr1.x, pr1.x), a1 = pk2(pr1.y, pr1.y);
            const ull a2 = pk2(pr1.z, pr1.z), a3 = pk2(pr1.w, pr1.w);
            ull s01 = mul2(a0, w0.x), s23 = mul2(a0, w0.y);
            s01 = fma2(a1, w1.x, s01);  s23 = fma2(a1, w1.y, s23);
            s01 = fma2(a2, w2.x, s01);  s23 = fma2(a2, w2.y, s23);
            s01 = fma2(a3, w3.x, s01);  s23 = fma2(a3, w3.y, s23);
            vB0[j] = s01; vB1[j] = s23;
        }
    }
    __syncthreads();   // acts ready

    for (int it = 0; it < 3; ++it) {
        // ---- M-step partials from register votes (6 i's, 8 values each) ----
        float S0 = 0.f;
        ull S1A0 = 0, S1A1 = 0, S1B0 = 0, S1B1 = 0;
        ull S2A0 = 0, S2A1 = 0, S2B0 = 0, S2B1 = 0;
        if (it == 0) {
            #pragma unroll
            for (int j = 0; j < 6; ++j) {
                const float rp = acts[i0 + j] * 0.0625f;
                const ull rp2 = pk2(rp, rp);
                S0 += rp;
                ull u;
                u = mul2(rp2, vA0[j]); S1A0 = add2(S1A0, u); S2A0 = fma2(u, vA0[j], S2A0);
                u = mul2(rp2, vA1[j]); S1A1 = add2(S1A1, u); S2A1 = fma2(u, vA1[j], S2A1);
                u = mul2(rp2, vB0[j]); S1B0 = add2(S1B0, u); S2B0 = fma2(u, vB0[j], S2B0);
                u = mul2(rp2, vB1[j]); S1B1 = add2(S1B1, u); S2B1 = fma2(u, vB1[j], S2B1);
            }
        } else {
            #pragma unroll
            for (int j = 0; j < 6; ++j) {
                const float rp = rr[(i0 + j) * 16 + om];   // already * acts (folded)
                const ull rp2 = pk2(rp, rp);
                S0 += rp;
                ull u;
                u = mul2(rp2, vA0[j]); S1A0 = add2(S1A0, u); S2A0 = fma2(u, vA0[j], S2A0);
                u = mul2(rp2, vA1[j]); S1A1 = add2(S1A1, u); S2A1 = fma2(u, vA1[j], S2A1);
                u = mul2(rp2, vB0[j]); S1B0 = add2(S1B0, u); S2B0 = fma2(u, vB0[j], S2B0);
                u = mul2(rp2, vB1[j]); S1B1 = add2(S1B1, u); S2B1 = fma2(u, vB1[j], S2B1);
            }
        }
        {
            // layout: pc1[h*256 + om*16 + p], p = pd*8 + r*4 + c
            const int f4 = h * 64 + om * 4 + pd * 2;   // float4 index
            ulonglong2 u;
            u.x = S1A0; u.y = S1A1; ((ulonglong2*)pc1)[f4]     = u;
            u.x = S1B0; u.y = S1B1; ((ulonglong2*)pc1)[f4 + 1] = u;
            u.x = S2A0; u.y = S2A1; ((ulonglong2*)pc2)[f4]     = u;
            u.x = S2B0; u.y = S2B1; ((ulonglong2*)pc2)[f4 + 1] = u;
            pc0[h * 32 + om * 2 + pd] = S0;
        }
        __syncthreads();

        // ---- stats phase: 256 threads, one (o,p) each, sqrt-free chain ----
        if (t < 256) {
            const int s0i = os * 2 + (ps >> 3);
            float s0 = 0.f, s1 = 0.f, s2 = 0.f;
            #pragma unroll
            for (int hh = 0; hh < 24; ++hh) {
                s1 += pc1[hh * 256 + t];
                s2 += pc2[hh * 256 + t];
                s0 += pc0[hh * 32 + s0i];
            }
            const float inv_rs = __fdividef(1.f, s0 + EPS);
            const float mean = s1 * inv_rs;
            float varsum = s2 - 2.f * mean * s1 + mean * mean * s0;
            varsum = fmaxf(varsum, 0.f);
            const float var = fmaxf(varsum * inv_rs, 1e-18f);     // sigma^2
            const float lg   = 0.5f * __logf(var);                // = log(sigma+~eps)
            const float invd = __fdividef(1.f, 2.f * var + EPS);
            const float av   = invd * LOG2E;
            const float bco  = mean * av;

            float L = lg, MBs = mean * bco;
            #pragma unroll
            for (int d = 8; d; d >>= 1) {
                L   += __shfl_xor_sync(0xffffffffu, L,   d);
                MBs += __shfl_xor_sync(0xffffffffu, MBs, d);
            }

            const float costsum = (16.f * beta_v[os] + L) * s0;
            const float itemp = 1.f + (float)it;
            const float oact = __fdividef(1.f, 1.f + __expf(-(itemp * (beta_a[os] - costsum))));

            if (it == 2) {
                out[n * 256 + t] = mean;
                if (ps == 0) out[NPOS * 256 + n * 16 + os] = oact;
            } else {
                a_sm[t] = av;
                b_sm[t] = bco;
                if (ps == 0) c_sm[os] = (__logf(oact + EPS) - L) * LOG2E - MBs;
            }
        }
        if (it == 2) return;
        __syncthreads();

        // ---- E-step cells from register votes ----
        {
            const int f4 = om * 4 + pd * 2;
            const ulonglong2 Ar0 = ((const ulonglong2*)a_sm)[f4];      // row 2pd
            const ulonglong2 Ar1 = ((const ulonglong2*)a_sm)[f4 + 1];  // row 2pd+1
            ulonglong2 Br0 = ((const ulonglong2*)b_sm)[f4];
            ulonglong2 Br1 = ((const ulonglong2*)b_sm)[f4 + 1];
            const ull n2 = pk2(-2.f, -2.f);
            const ull BA0 = mul2(Br0.x, n2), BA1 = mul2(Br0.y, n2);
            const ull BB0 = mul2(Br1.x, n2), BB1 = mul2(Br1.y, n2);
            const float C2 = c_sm[om] * 0.5f;
            #pragma unroll
            for (int j = 0; j < 6; ++j) {
                ull s = mul2(vA0[j], fma2(vA0[j], Ar0.x, BA0));
                s = fma2(vA1[j], fma2(vA1[j], Ar0.y, BA1), s);
                s = fma2(vB0[j], fma2(vB0[j], Ar1.x, BB0), s);
                s = fma2(vB1[j], fma2(vB1[j], Ar1.y, BB1), s);
                float lo, hi; upk2(s, lo, hi);
                ep[(i0 + j) * 36 + om * 2 + pd] = C2 - (lo + hi);
            }
        }
        __syncthreads();

        // ---- paired-lane softmax: lanes (2i, 2i+1) split the 16 o's ----
        if (t < 2 * ICAP) {
            const int i = t >> 1, half = t & 1;
            const float4* eprow = (const float4*)(ep + i * 36) + half * 4;
            float z[8];
            float mx = -3.4e38f;
            #pragma unroll
            for (int k = 0; k < 4; ++k) {
                const int kk = (k + 2 * half) & 3;        // bank stagger between halves
                const float4 P = eprow[kk];               // cells (2o,2o+1) pairs
                const float z0 = P.x + P.y;
                const float z1 = P.z + P.w;
                z[kk * 2] = z0; z[kk * 2 + 1] = z1;
                mx = fmaxf(mx, fmaxf(z0, z1));
            }
            mx = fmaxf(mx, __shfl_xor_sync(0xffffffffu, mx, 1));
            float ss = 0.f;
            #pragma unroll
            for (int k = 0; k < 8; ++k) {
                z[k] = exp2f(z[k] - mx);
                ss += z[k];
            }
            ss += __shfl_xor_sync(0xffffffffu, ss, 1);
            const float scale = acts[i] * __fdividef(1.f, ss);   // fold acts into rr
            float4 r0, r1;
            r0.x = z[0] * scale; r0.y = z[1] * scale; r0.z = z[2] * scale; r0.w = z[3] * scale;
            r1.x = z[4] * scale; r1.y = z[5] * scale; r1.z = z[6] * scale; r1.w = z[7] * scale;
            float4* dst = (float4*)(rr + i * 16 + half * 8);
            dst[0] = r0; dst[1] = r1;
        }
        __syncthreads();
    }
}

extern "C" void kernel_launch(void* const* d_in, const int* in_sizes, int n_in,
                              void* d_out, int out_size) {
    const float* pose_in = (const float*)d_in[0];
    const float* act_in  = (const float*)d_in[1];
    const float* w       = (const float*)d_in[2];
    const float* beta_v  = (const float*)d_in[3];
    const float* beta_a  = (const float*)d_in[4];
    float* out = (float*)d_out;

    transpose_w_kernel<<<36, 256>>>(w);

    cudaFuncSetAttribute(caps_em_kernel,
                         cudaFuncAttributeMaxDynamicSharedMemorySize, SMEM_BYTES);
    caps_em_kernel<<<NPOS, 768, SMEM_BYTES>>>(pose_in, act_in, beta_v, beta_a, out);
}

// round 17
// speedup vs baseline: 1.0029x; 1.0029x over previous
#include <cuda_runtime.h>
#include <math.h>
#include <stdint.h>

// ConvolutionalCapsule EM routing, R12: hybrid register/smem votes ->
// 64 regs/thread -> TWO independent CTAs per SM (512 thr each).
// t = h*32 + om*2 + pd (h 0..15, i = h*9 + j). Per (i,om,pd):
//   row 2pd   (4 floats) in registers (vA0,vA1 packed f32x2)
//   row 2pd+1 (4 floats) in smem vs[i*32+om*2+pd] (warp-consecutive float4s)
// pc reduced to [8] slots via pairwise precombine; ep unioned over pc.
// Pre-transposed w (g_wT), sqrt-free stats, paired-lane softmax.

#define EPS 1e-9f
#define LOG2E 1.4426950408889634f
#define NPOS 1152
#define ICAP 144

// smem float offsets (per CTA: 26624 floats = 106496 B; 2 CTAs = 213 KB/SM)
#define OFF_VS    0        // votes half: [144][32] float4 cells = 18432 floats
#define OFF_RR    18432    // [144][16] rr (softmax output)
#define OFF_ACTS  20736    // [144] (+pad)
#define OFF_BASE  20896    // [16] int row-base table (9 used)
#define OFF_PC1   20912    // S1: [8][256]   (lifetime: M-store -> stats)
#define OFF_PC2   22960    // S2: [8][256]
#define OFF_PC0   25008    // S0: [8][32]
#define OFF_EP    20912    // ep [144][36] = 5184, UNION with pc (disjoint lifetime)
#define OFF_A     26096    // [256] av  (o*16+p)
#define OFF_B     26352    // [256] bco
#define OFF_C     26608    // [16]
#define SMEM_FLOATS 26624
#define SMEM_BYTES (SMEM_FLOATS * 4)

typedef unsigned long long ull;

// transposed weights: wT[i][r][om] as float4 (ulonglong2) blocks
__device__ ulonglong2 g_wT[144 * 64];

__device__ __forceinline__ ull pk2(float lo, float hi) {
    ull d;
    asm("mov.b64 %0, {%1, %2};" : "=l"(d)
        : "r"(__float_as_uint(lo)), "r"(__float_as_uint(hi)));
    return d;
}
__device__ __forceinline__ void upk2(ull v, float& lo, float& hi) {
    unsigned a, b;
    asm("mov.b64 {%0, %1}, %2;" : "=r"(a), "=r"(b) : "l"(v));
    lo = __uint_as_float(a); hi = __uint_as_float(b);
}
__device__ __forceinline__ ull fma2(ull a, ull b, ull c) {
    ull d; asm("fma.rn.f32x2 %0, %1, %2, %3;" : "=l"(d) : "l"(a), "l"(b), "l"(c));
    return d;
}
__device__ __forceinline__ ull mul2(ull a, ull b) {
    ull d; asm("mul.rn.f32x2 %0, %1, %2;" : "=l"(d) : "l"(a), "l"(b));
    return d;
}
__device__ __forceinline__ ull add2(ull a, ull b) {
    ull d; asm("add.rn.f32x2 %0, %1, %2;" : "=l"(d) : "l"(a), "l"(b));
    return d;
}

__global__ void transpose_w_kernel(const float* __restrict__ w) {
    const int idx = blockIdx.x * 1024 + threadIdx.x;   // 9216 float4s
    if (idx < 144 * 64) {
        const int i  = idx >> 6;
        const int rm = idx & 63;
        const int r  = rm >> 4;
        const int om = rm & 15;
        g_wT[idx] = ((const ulonglong2*)w)[i * 64 + om * 4 + r];
    }
}

__global__ __launch_bounds__(512, 2)
void caps_em_kernel(const float* __restrict__ pose_in,   // [8,14,14,256]
                    const float* __restrict__ act_in,    // [8,14,14,16]
                    const float* __restrict__ beta_v,    // [16]
                    const float* __restrict__ beta_a,    // [16]
                    float* __restrict__ out)             // pose[1152,256] ++ act[1152,16]
{
    extern __shared__ float sm[];
    ulonglong2* vs  = (ulonglong2*)(sm + OFF_VS);   // [i*32 + om*2 + pd]
    float* rr    = sm + OFF_RR;
    float* acts  = sm + OFF_ACTS;
    int*   baseK = (int*)(sm + OFF_BASE);
    float* pc1   = sm + OFF_PC1;
    float* pc2   = sm + OFF_PC2;
    float* pc0   = sm + OFF_PC0;
    float* ep    = sm + OFF_EP;
    float* a_sm  = sm + OFF_A;
    float* b_sm  = sm + OFF_B;
    float* c_sm  = sm + OFF_C;

    const int n = blockIdx.x;
    const int x = n % 12;
    const int y = (n / 12) % 12;
    const int b = n / 144;
    const int t = threadIdx.x;

    const int h  = t >> 5;          // 0..15: i = h*9 + j
    const int om = (t >> 1) & 15;   // output capsule
    const int pd = t & 1;           // row pair: regs row 2pd, smem row 2pd+1
    const int i0 = h * 9;
    const int cell0 = i0 * 32 + om * 2 + pd;
    // stats mapping (t < 256)
    const int os = t >> 4;
    const int ps = t & 15;

    // ---- row-base table (9 kernel positions) ----
    if (t < 9)
        baseK[t] = (b * 14 + (y + t / 3)) * 14 + (x + t % 3);
    __syncthreads();

    // ---- stage acts ----
    if (t < ICAP)
        acts[t] = act_in[baseK[t >> 4] * 16 + (t & 15)];

    // ---- build votes: row 2pd -> regs, row 2pd+1 -> smem ----
    ull vA0[9], vA1[9];
    #pragma unroll
    for (int j = 0; j < 9; ++j) {
        const int i = i0 + j;
        const float* pp = pose_in + (size_t)baseK[i >> 4] * 256 + (i & 15) * 16 + pd * 8;
        const float4 pr0 = *(const float4*)pp;        // row 2pd
        const float4 pr1 = *(const float4*)(pp + 4);  // row 2pd+1
        const ulonglong2* wt = g_wT + (size_t)i * 64 + om;
        const ulonglong2 w0 = wt[0], w1 = wt[16], w2 = wt[32], w3 = wt[48];
        // row 2pd+1 first (store to smem, free the regs)
        {
            const ull a0 = pk2(pr1.x, pr1.x), a1 = pk2(pr1.y, pr1.y);
            const ull a2 = pk2(pr1.z, pr1.z), a3 = pk2(pr1.w, pr1.w);
            ull s01 = mul2(a0, w0.x), s23 = mul2(a0, w0.y);
            s01 = fma2(a1, w1.x, s01);  s23 = fma2(a1, w1.y, s23);
            s01 = fma2(a2, w2.x, s01);  s23 = fma2(a2, w2.y, s23);
            s01 = fma2(a3, w3.x, s01);  s23 = fma2(a3, w3.y, s23);
            ulonglong2 u; u.x = s01; u.y = s23;
            vs[cell0 + j * 32] = u;
        }
        // row 2pd -> registers
        {
            const ull a0 = pk2(pr0.x, pr0.x), a1 = pk2(pr0.y, pr0.y);
            const ull a2 = pk2(pr0.z, pr0.z), a3 = pk2(pr0.w, pr0.w);
            ull s01 = mul2(a0, w0.x), s23 = mul2(a0, w0.y);
            s01 = fma2(a1, w1.x, s01);  s23 = fma2(a1, w1.y, s23);
            s01 = fma2(a2, w2.x, s01);  s23 = fma2(a2, w2.y, s23);
            s01 = fma2(a3, w3.x, s01);  s23 = fma2(a3, w3.y, s23);
            vA0[j] = s01; vA1[j] = s23;
        }
    }
    __syncthreads();   // acts + smem votes ready

    for (int it = 0; it < 3; ++it) {
        // ---- M-step partials (reg row + smem row) ----
        float S0 = 0.f;
        ull S1A0 = 0, S1A1 = 0, S2A0 = 0, S2A1 = 0;
        ull S1B0 = 0, S1B1 = 0, S2B0 = 0, S2B1 = 0;
        if (it == 0) {
            #pragma unroll
            for (int j = 0; j < 9; ++j) {
                const float rp = acts[i0 + j] * 0.0625f;
                const ull rp2 = pk2(rp, rp);
                S0 += rp;
                ull u;
                u = mul2(rp2, vA0[j]); S1A0 = add2(S1A0, u); S2A0 = fma2(u, vA0[j], S2A0);
                u = mul2(rp2, vA1[j]); S1A1 = add2(S1A1, u); S2A1 = fma2(u, vA1[j], S2A1);
                const ulonglong2 vb = vs[cell0 + j * 32];
                u = mul2(rp2, vb.x); S1B0 = add2(S1B0, u); S2B0 = fma2(u, vb.x, S2B0);
                u = mul2(rp2, vb.y); S1B1 = add2(S1B1, u); S2B1 = fma2(u, vb.y, S2B1);
            }
        } else {
            #pragma unroll
            for (int j = 0; j < 9; ++j) {
                const float rp = rr[(i0 + j) * 16 + om];   // already * acts (folded)
                const ull rp2 = pk2(rp, rp);
                S0 += rp;
                ull u;
                u = mul2(rp2, vA0[j]); S1A0 = add2(S1A0, u); S2A0 = fma2(u, vA0[j], S2A0);
                u = mul2(rp2, vA1[j]); S1A1 = add2(S1A1, u); S2A1 = fma2(u, vA1[j], S2A1);
                const ulonglong2 vb = vs[cell0 + j * 32];
                u = mul2(rp2, vb.x); S1B0 = add2(S1B0, u); S2B0 = fma2(u, vb.x, S2B0);
                u = mul2(rp2, vb.y); S1B1 = add2(S1B1, u); S2B1 = fma2(u, vb.y, S2B1);
            }
        }
        // ---- pairwise precombine into pc[8] slots ----
        // p layout: pc1[hh*256 + om*16 + p], p = pd*8 + {row2pd cols, row2pd+1 cols}
        const int f4 = (h & 7) * 64 + om * 4 + pd * 2;
        if (h >= 8) {
            ulonglong2 u2;
            u2.x = S1A0; u2.y = S1A1; ((ulonglong2*)pc1)[f4]     = u2;
            u2.x = S1B0; u2.y = S1B1; ((ulonglong2*)pc1)[f4 + 1] = u2;
            u2.x = S2A0; u2.y = S2A1; ((ulonglong2*)pc2)[f4]     = u2;
            u2.x = S2B0; u2.y = S2B1; ((ulonglong2*)pc2)[f4 + 1] = u2;
            pc0[(h - 8) * 32 + om * 2 + pd] = S0;
        }
        __syncthreads();
        if (h < 8) {
            ulonglong2 l;
            l = ((ulonglong2*)pc1)[f4];     l.x = add2(l.x, S1A0); l.y = add2(l.y, S1A1);
            ((ulonglong2*)pc1)[f4] = l;
            l = ((ulonglong2*)pc1)[f4 + 1]; l.x = add2(l.x, S1B0); l.y = add2(l.y, S1B1);
            ((ulonglong2*)pc1)[f4 + 1] = l;
            l = ((ulonglong2*)pc2)[f4];     l.x = add2(l.x, S2A0); l.y = add2(l.y, S2A1);
            ((ulonglong2*)pc2)[f4] = l;
            l = ((ulonglong2*)pc2)[f4 + 1]; l.x = add2(l.x, S2B0); l.y = add2(l.y, S2B1);
            ((ulonglong2*)pc2)[f4 + 1] = l;
            pc0[h * 32 + om * 2 + pd] += S0;
        }
        __syncthreads();

        // ---- stats phase: 256 threads, one (o,p) each, sqrt-free ----
        if (t < 256) {
            const int s0i = os * 2 + (ps >> 3);
            float s0 = 0.f, s1 = 0.f, s2 = 0.f;
            #pragma unroll
            for (int hh = 0; hh < 8; ++hh) {
                s1 += pc1[hh * 256 + t];
                s2 += pc2[hh * 256 + t];
                s0 += pc0[hh * 32 + s0i];
            }
            const float inv_rs = __fdividef(1.f, s0 + EPS);
            const float mean = s1 * inv_rs;
            float varsum = s2 - 2.f * mean * s1 + mean * mean * s0;
            varsum = fmaxf(varsum, 0.f);
            const float var = fmaxf(varsum * inv_rs, 1e-18f);     // sigma^2
            const float lg   = 0.5f * __logf(var);                // = log(sigma+~eps)
            const float invd = __fdividef(1.f, 2.f * var + EPS);
            const float av   = invd * LOG2E;
            const float bco  = mean * av;

            float L = lg, MBs = mean * bco;
            #pragma unroll
            for (int d = 8; d; d >>= 1) {
                L   += __shfl_xor_sync(0xffffffffu, L,   d);
                MBs += __shfl_xor_sync(0xffffffffu, MBs, d);
            }

            const float costsum = (16.f * beta_v[os] + L) * s0;
            const float itemp = 1.f + (float)it;
            const float oact = __fdividef(1.f, 1.f + __expf(-(itemp * (beta_a[os] - costsum))));

            if (it == 2) {
                out[n * 256 + t] = mean;
                if (ps == 0) out[NPOS * 256 + n * 16 + os] = oact;
            } else {
                a_sm[t] = av;
                b_sm[t] = bco;
                if (ps == 0) c_sm[os] = (__logf(oact + EPS) - L) * LOG2E - MBs;
            }
        }
        if (it == 2) return;
        __syncthreads();   // also orders pc-reads before ep-writes (union)

        // ---- E-step cells (reg row + smem row) ----
        {
            const int f4c = om * 4 + pd * 2;
            const ulonglong2 Ar0 = ((const ulonglong2*)a_sm)[f4c];      // row 2pd
            const ulonglong2 Ar1 = ((const ulonglong2*)a_sm)[f4c + 1];  // row 2pd+1
            const ulonglong2 Br0 = ((const ulonglong2*)b_sm)[f4c];
            const ulonglong2 Br1 = ((const ulonglong2*)b_sm)[f4c + 1];
            const ull n2 = pk2(-2.f, -2.f);
            const ull BA0 = mul2(Br0.x, n2), BA1 = mul2(Br0.y, n2);
            const ull BB0 = mul2(Br1.x, n2), BB1 = mul2(Br1.y, n2);
            const float C2 = c_sm[om] * 0.5f;
            #pragma unroll
            for (int j = 0; j < 9; ++j) {
                ull s = mul2(vA0[j], fma2(vA0[j], Ar0.x, BA0));
                s = fma2(vA1[j], fma2(vA1[j], Ar0.y, BA1), s);
                const ulonglong2 vb = vs[cell0 + j * 32];
                s = fma2(vb.x, fma2(vb.x, Ar1.x, BB0), s);
                s = fma2(vb.y, fma2(vb.y, Ar1.y, BB1), s);
                float lo, hi; upk2(s, lo, hi);
                ep[(i0 + j) * 36 + om * 2 + pd] = C2 - (lo + hi);
            }
        }
        __syncthreads();

        // ---- paired-lane softmax: lanes (2i, 2i+1) split the 16 o's ----
        if (t < 2 * ICAP) {
            const int i = t >> 1, half = t & 1;
            const float4* eprow = (const float4*)(ep + i * 36) + half * 4;
            float z[8];
            float mx = -3.4e38f;
            #pragma unroll
            for (int k = 0; k < 4; ++k) {
                const int kk = (k + 2 * half) & 3;        // bank stagger between halves
                const float4 P = eprow[kk];               // cells (2o,2o+1) pairs
                const float z0 = P.x + P.y;
                const float z1 = P.z + P.w;
                z[kk * 2] = z0; z[kk * 2 + 1] = z1;
                mx = fmaxf(mx, fmaxf(z0, z1));
            }
            mx = fmaxf(mx, __shfl_xor_sync(0xffffffffu, mx, 1));
            float ss = 0.f;
            #pragma unroll
            for (int k = 0; k < 8; ++k) {
                z[k] = exp2f(z[k] - mx);
                ss += z[k];
            }
            ss += __shfl_xor_sync(0xffffffffu, ss, 1);
            const float scale = acts[i] * __fdividef(1.f, ss);   // fold acts into rr
            float4 r0, r1;
            r0.x = z[0] * scale; r0.y = z[1] * scale; r0.z = z[2] * scale; r0.w = z[3] * scale;
            r1.x = z[4] * scale; r1.y = z[5] * scale; r1.z = z[6] * scale; r1.w = z[7] * scale;
            float4* dst = (float4*)(rr + i * 16 + half * 8);
            dst[0] = r0; dst[1] = r1;
        }
        __syncthreads();
    }
}

extern "C" void kernel_launch(void* const* d_in, const int* in_sizes, int n_in,
                              void* d_out, int out_size) {
    const float* pose_in = (const float*)d_in[0];
    const float* act_in  = (const float*)d_in[1];
    const float* w       = (const float*)d_in[2];
    const float* beta_v  = (const float*)d_in[3];
    const float* beta_a  = (const float*)d_in[4];
    float* out = (float*)d_out;

    transpose_w_kernel<<<9, 1024>>>(w);

    cudaFuncSetAttribute(caps_em_kernel,
                         cudaFuncAttributeMaxDynamicSharedMemorySize, SMEM_BYTES);
    caps_em_kernel<<<NPOS, 512, SMEM_BYTES>>>(pose_in, act_in, beta_v, beta_a, out);
}